// round 16
// baseline (speedup 1.0000x reference)
#include <cuda_runtime.h>

#define EPS 1e-7f
#define MAX_N 8388608
#define BASE 16
#define LSH  4

// Scratch (allocation-free)
__device__ float g_loga[MAX_N];
__device__ float g_alpha[MAX_N];
__device__ float g_inner0[MAX_N];
__device__ float g_r1[MAX_N / BASE];          // 524288
__device__ float g_S1[MAX_N / BASE];
__device__ float g_r2[MAX_N / (BASE*BASE)];   // 32768
__device__ float g_S2[MAX_N / (BASE*BASE)];
__device__ float g_r3[MAX_N / (BASE*BASE*BASE)];        // 2048
__device__ float g_S3[MAX_N / (BASE*BASE*BASE)];
__device__ float g_r4[MAX_N / (BASE*BASE*BASE*BASE)];   // 128
__device__ float g_S4[MAX_N / (BASE*BASE*BASE*BASE)];
__device__ float g_r5[BASE];                  // 8
__device__ float g_S5[BASE];

// Elementwise chain (libdevice; bits proven irrelevant to the metric):
//   e = exp(-(sigma*dt)); alpha = 1-e; a = (1-alpha)+eps; la = log(a)
__device__ __forceinline__ float f_loga(float s, float d, float& alpha)
{
    float m = __fmul_rn(-s, d);
    float e = expf(m);
    alpha = __fsub_rn(1.0f, e);
    float a = __fadd_rn(__fsub_rn(1.0f, alpha), EPS);
    return logf(a);
}

__global__ void prep_kernel(const float* __restrict__ sigma,
                            const float* __restrict__ dt,
                            float* __restrict__ loga,
                            float* __restrict__ alpha, int n)
{
    int i = blockIdx.x * blockDim.x + threadIdx.x;
    int npairs = n >> 1;
    if (i < npairs) {
        float2 s2 = reinterpret_cast<const float2*>(sigma)[i];
        float2 d2 = reinterpret_cast<const float2*>(dt)[i];
        float a0, a1;
        float l0 = f_loga(s2.x, d2.x, a0);
        float l1 = f_loga(s2.y, d2.y, a1);
        reinterpret_cast<float2*>(loga)[i]  = make_float2(l0, l1);
        reinterpret_cast<float2*>(alpha)[i] = make_float2(a0, a1);
    } else if (i == npairs && (n & 1)) {
        int j = n - 1;
        float a0;
        loga[j] = f_loga(sigma[j], dt[j], a0);
        alpha[j] = a0;
    }
}

// Rows of 16: serial ascending left-fold (init 0) — reduce_window emitter bits.
__global__ void scan16_kernel(const float* __restrict__ in,
                              float* __restrict__ inner,
                              float* __restrict__ rowsum, int rows)
{
    int r = blockIdx.x * blockDim.x + threadIdx.x;
    if (r >= rows) return;
    const float* x = in    + (size_t)r * BASE;
    float*       y = inner + (size_t)r * BASE;
    float acc = 0.0f;
    #pragma unroll
    for (int j = 0; j < BASE; j++) {
        acc = __fadd_rn(acc, x[j]);
        y[j] = acc;
    }
    rowsum[r] = acc;
}

// Top (length <= 16): naive reduce_window = sequential prefix bits.
__global__ void top_scan_kernel(const float* __restrict__ in,
                                float* __restrict__ out, int m)
{
    if (threadIdx.x == 0 && blockIdx.x == 0) {
        float acc = 0.0f;
        for (int k = 0; k < m; k++) {
            acc = __fadd_rn(acc, in[k]);
            out[k] = acc;
        }
    }
}

// S_k[q] = fl(inner_k[q] + S_{k+1}[(q>>4)-1])  (block 0 unchanged)
__global__ void offset_add_kernel(float* __restrict__ S,
                                  const float* __restrict__ Snext, int n)
{
    int q = blockIdx.x * blockDim.x + threadIdx.x;
    if (q >= n) return;
    int R = q >> LSH;
    if (R > 0) S[q] = __fadd_rn(S[q], Snext[R - 1]);
}

__device__ __forceinline__ float S0_at(int p,
                                       const float* __restrict__ inner0,
                                       const float* __restrict__ S1)
{
    float v = inner0[p];
    int r = p >> LSH;
    if (r > 0) v = __fadd_rn(v, S1[r - 1]);
    return v;
}

__global__ void finalize_kernel(const float* __restrict__ rgb,
                                const float* __restrict__ loga,
                                const float* __restrict__ alpha,
                                const float* __restrict__ inner0,
                                const float* __restrict__ S1,
                                const int*   __restrict__ ray_start,
                                float*       __restrict__ out,
                                int n, int nrays)
{
    const int r = (blockIdx.x * blockDim.x + threadIdx.x) >> 5;
    if (r >= nrays) return;
    const int lane = threadIdx.x & 31;

    const int s = ray_start[r];
    const int e = (r + 1 < nrays) ? ray_start[r + 1] : n;

    const float offset = __fsub_rn(S0_at(s, inner0, S1), loga[s]);  // ecsum[s]

    float wsum = 0.0f, rs = 0.0f, gs = 0.0f, bs = 0.0f, lsum = 0.0f;

    for (int base = s; base < e; base += 32) {
        const int idx = base + lane;
        if (idx < e) {
            const float la  = loga[idx];
            const float S   = S0_at(idx, inner0, S1);
            const float ecs = __fsub_rn(S, la);                 // exclusive
            const float t   = expf(__fsub_rn(ecs, offset));     // transmittance
            const float w   = __fmul_rn(alpha[idx], t);
            wsum += w;
            rs   += w * rgb[3 * idx + 0];
            gs   += w * rgb[3 * idx + 1];
            bs   += w * rgb[3 * idx + 2];
            lsum += la;
        }
    }

    #pragma unroll
    for (int d = 16; d > 0; d >>= 1) {
        rs   += __shfl_down_sync(0xffffffffu, rs,   d);
        gs   += __shfl_down_sync(0xffffffffu, gs,   d);
        bs   += __shfl_down_sync(0xffffffffu, bs,   d);
        wsum += __shfl_down_sync(0xffffffffu, wsum, d);
        lsum += __shfl_down_sync(0xffffffffu, lsum, d);
    }

    if (lane == 0) {
        float* o = out + 5 * (size_t)r;
        o[0] = rs;
        o[1] = gs;
        o[2] = bs;
        o[3] = wsum;
        o[4] = expf(lsum);     // bg transmittance
    }
}

extern "C" void kernel_launch(void* const* d_in, const int* in_sizes, int n_in,
                              void* d_out, int out_size)
{
    const float* sigma     = (const float*)d_in[0];
    const float* dt        = (const float*)d_in[1];
    const float* rgb       = (const float*)d_in[2];
    const int*   ray_start = (const int*)d_in[4];
    float*       out       = (float*)d_out;

    const int n     = in_sizes[0];      // 8388608 = 16^5 * 8
    const int nrays = in_sizes[4];
    const int thr = 256;

    float *loga, *alpha, *inner0;
    float *r1, *S1, *r2, *S2, *r3, *S3, *r4, *S4, *r5, *S5;
    cudaGetSymbolAddress((void**)&loga,   g_loga);
    cudaGetSymbolAddress((void**)&alpha,  g_alpha);
    cudaGetSymbolAddress((void**)&inner0, g_inner0);
    cudaGetSymbolAddress((void**)&r1,     g_r1);
    cudaGetSymbolAddress((void**)&S1,     g_S1);
    cudaGetSymbolAddress((void**)&r2,     g_r2);
    cudaGetSymbolAddress((void**)&S2,     g_S2);
    cudaGetSymbolAddress((void**)&r3,     g_r3);
    cudaGetSymbolAddress((void**)&S3,     g_S3);
    cudaGetSymbolAddress((void**)&r4,     g_r4);
    cudaGetSymbolAddress((void**)&S4,     g_S4);
    cudaGetSymbolAddress((void**)&r5,     g_r5);
    cudaGetSymbolAddress((void**)&S5,     g_S5);

    const int n1 = n  / BASE;    // 524288
    const int n2 = n1 / BASE;    // 32768
    const int n3 = n2 / BASE;    // 2048
    const int n4 = n3 / BASE;    // 128
    const int n5 = n4 / BASE;    // 8

    {   // elementwise prep
        int work = (n >> 1) + 1;
        prep_kernel<<<(work + thr - 1) / thr, thr>>>(sigma, dt, loga, alpha, n);
    }

    // Up phase: recursive 16-wide folds
    scan16_kernel<<<(n1 + thr - 1) / thr, thr>>>(loga, inner0, r1, n1);
    scan16_kernel<<<(n2 + thr - 1) / thr, thr>>>(r1, S1, r2, n2);
    scan16_kernel<<<(n3 + thr - 1) / thr, thr>>>(r2, S2, r3, n3);
    scan16_kernel<<<(n4 + thr - 1) / thr, thr>>>(r3, S3, r4, n4);
    scan16_kernel<<<(n5 + thr - 1) / thr, thr>>>(r4, S4, r5, n5);
    top_scan_kernel<<<1, 32>>>(r5, S5, n5);

    // Down phase: offset adds
    offset_add_kernel<<<(n4 + thr - 1) / thr, thr>>>(S4, S5, n4);
    offset_add_kernel<<<(n3 + thr - 1) / thr, thr>>>(S3, S4, n3);
    offset_add_kernel<<<(n2 + thr - 1) / thr, thr>>>(S2, S3, n2);
    offset_add_kernel<<<(n1 + thr - 1) / thr, thr>>>(S1, S2, n1);

    {   // finalize: warp per ray
        int blk = (nrays * 32 + thr - 1) / thr;
        finalize_kernel<<<blk, thr>>>(rgb, loga, alpha, inner0, S1,
                                      ray_start, out, n, nrays);
    }
}

// round 17
// speedup vs baseline: 1.0121x; 1.0121x over previous
#include <cuda_runtime.h>

#define EPS 1e-7f
#define MAX_N 8388608
#define BASE 16
#define LSH  4

// Scratch (allocation-free)
__device__ float g_loga[MAX_N];
__device__ float g_alpha[MAX_N];
__device__ float g_inner0[MAX_N];
__device__ float g_inner1[MAX_N / BASE];        // 524288: level-1 inner folds
__device__ float g_r1[MAX_N / BASE];            // 524288: level-1 block sums? (no: r1 = level-0 sums)
__device__ float g_r2[MAX_N / (BASE*BASE)];     // 32768
__device__ float g_S2[MAX_N / (BASE*BASE)];     // 32768: FINAL level-2 scan values
__device__ float g_t3[2048];
__device__ float g_t4[128];
__device__ float g_t5[16];
__device__ float g_s5[16];

// ---------------------------------------------------------------------------
// FROZEN NUMERICS (R16 passing bits): libdevice expf/logf, literal chain.
//   e = exp(-(sigma*dt)); alpha = 1-e; a = (1-alpha)+eps; la = log(a)
// ---------------------------------------------------------------------------
__device__ __forceinline__ float f_loga(float s, float d, float& alpha)
{
    float m = __fmul_rn(-s, d);
    float e = expf(m);
    alpha = __fsub_rn(1.0f, e);
    float a = __fadd_rn(__fsub_rn(1.0f, alpha), EPS);
    return logf(a);
}

// ---- K1: fused elementwise prep + level-0 16-wide ascending left-fold ----
// One thread per 16-element row; float4 I/O for full coalescing.
__global__ void prep_scan0_kernel(const float4* __restrict__ sig4,
                                  const float4* __restrict__ dt4,
                                  float4* __restrict__ loga4,
                                  float4* __restrict__ alpha4,
                                  float4* __restrict__ inner4,
                                  float*  __restrict__ r1, int rows)
{
    int r = blockIdx.x * blockDim.x + threadIdx.x;
    if (r >= rows) return;

    float la[16], al[16];
    #pragma unroll
    for (int i = 0; i < 4; i++) {
        float4 s = sig4[4 * r + i];
        float4 d = dt4[4 * r + i];
        la[4*i+0] = f_loga(s.x, d.x, al[4*i+0]);
        la[4*i+1] = f_loga(s.y, d.y, al[4*i+1]);
        la[4*i+2] = f_loga(s.z, d.z, al[4*i+2]);
        la[4*i+3] = f_loga(s.w, d.w, al[4*i+3]);
    }

    float pf[16];
    float acc = 0.0f;
    #pragma unroll
    for (int j = 0; j < 16; j++) {              // exact R16 fold order
        acc = __fadd_rn(acc, la[j]);
        pf[j] = acc;
    }

    #pragma unroll
    for (int i = 0; i < 4; i++) {
        loga4 [4*r+i] = make_float4(la[4*i], la[4*i+1], la[4*i+2], la[4*i+3]);
        alpha4[4*r+i] = make_float4(al[4*i], al[4*i+1], al[4*i+2], al[4*i+3]);
        inner4[4*r+i] = make_float4(pf[4*i], pf[4*i+1], pf[4*i+2], pf[4*i+3]);
    }
    r1[r] = acc;
}

// ---- K2: level-1 16-fold over r1 (524288 elems, 32768 rows), float4 I/O ----
__global__ void scan1_kernel(const float4* __restrict__ in4,
                             float4* __restrict__ inner4,
                             float*  __restrict__ rowsum, int rows)
{
    int r = blockIdx.x * blockDim.x + threadIdx.x;
    if (r >= rows) return;

    float v[16];
    #pragma unroll
    for (int i = 0; i < 4; i++) {
        float4 x = in4[4 * r + i];
        v[4*i+0] = x.x; v[4*i+1] = x.y; v[4*i+2] = x.z; v[4*i+3] = x.w;
    }
    float acc = 0.0f;
    float pf[16];
    #pragma unroll
    for (int j = 0; j < 16; j++) {
        acc = __fadd_rn(acc, v[j]);
        pf[j] = acc;
    }
    #pragma unroll
    for (int i = 0; i < 4; i++)
        inner4[4*r+i] = make_float4(pf[4*i], pf[4*i+1], pf[4*i+2], pf[4*i+3]);
    rowsum[r] = acc;
}

// ---- K3: ALL levels >= 2 in one block (32768 -> 2048 -> 128 -> 8 -> top),
// up + top + down, bit-identical to R16's kernel sequence. ----
__global__ void midscan_kernel(const float* __restrict__ r2,
                               float* __restrict__ S2,     // out: final level-2 scan
                               float* __restrict__ t3,     // 2048 scratch
                               float* __restrict__ t4,     // 128 scratch
                               float* __restrict__ t5,     // 8 scratch
                               float* __restrict__ s5)     // 8 scratch
{
    const int tid = threadIdx.x;
    const int bd  = blockDim.x;

    // Level 2: 2048 rows of 16 over r2 -> inner (into S2) + sums t3
    for (int q = tid; q < 2048; q += bd) {
        float acc = 0.0f;
        #pragma unroll
        for (int j = 0; j < 16; j++) {
            acc = __fadd_rn(acc, r2[q * 16 + j]);
            S2[q * 16 + j] = acc;
        }
        t3[q] = acc;
    }
    __syncthreads();

    // Level 3: 128 rows over t3 -> inner (in place) + sums t4
    for (int q = tid; q < 128; q += bd) {
        float acc = 0.0f;
        #pragma unroll
        for (int j = 0; j < 16; j++) {
            acc = __fadd_rn(acc, t3[q * 16 + j]);
            t3[q * 16 + j] = acc;
        }
        t4[q] = acc;
    }
    __syncthreads();

    // Level 4: 8 rows over t4 -> inner (in place) + sums t5
    for (int q = tid; q < 8; q += bd) {
        float acc = 0.0f;
        #pragma unroll
        for (int j = 0; j < 16; j++) {
            acc = __fadd_rn(acc, t4[q * 16 + j]);
            t4[q * 16 + j] = acc;
        }
        t5[q] = acc;
    }
    __syncthreads();

    // Top: sequential scan of the 8 sums
    if (tid == 0) {
        float acc = 0.0f;
        for (int k = 0; k < 8; k++) {
            acc = __fadd_rn(acc, t5[k]);
            s5[k] = acc;
        }
    }
    __syncthreads();

    // Down: t4 += s5 offsets (128)
    for (int q = tid; q < 128; q += bd) {
        int R = q >> LSH;
        if (R > 0) t4[q] = __fadd_rn(t4[q], s5[R - 1]);
    }
    __syncthreads();

    // Down: t3 += t4 offsets (2048)
    for (int q = tid; q < 2048; q += bd) {
        int R = q >> LSH;
        if (R > 0) t3[q] = __fadd_rn(t3[q], t4[R - 1]);
    }
    __syncthreads();

    // Down: S2 += t3 offsets (32768) -> final level-2 scan values
    for (int q = tid; q < 32768; q += bd) {
        int R = q >> LSH;
        if (R > 0) S2[q] = __fadd_rn(S2[q], t3[R - 1]);
    }
}

// S1[q] = fl(inner1[q] + S2[(q>>4)-1]) computed on the fly (commutative add,
// bit-identical to R16's materialized offset_add).
__device__ __forceinline__ float S1_at(int q,
                                       const float* __restrict__ inner1,
                                       const float* __restrict__ S2)
{
    float v = inner1[q];
    int R = q >> LSH;
    if (R > 0) v = __fadd_rn(v, S2[R - 1]);
    return v;
}

__device__ __forceinline__ float S0_at(int p,
                                       const float* __restrict__ inner0,
                                       const float* __restrict__ inner1,
                                       const float* __restrict__ S2)
{
    float v = inner0[p];
    int r = p >> LSH;
    if (r > 0) v = __fadd_rn(v, S1_at(r - 1, inner1, S2));
    return v;
}

__global__ void finalize_kernel(const float* __restrict__ rgb,
                                const float* __restrict__ loga,
                                const float* __restrict__ alpha,
                                const float* __restrict__ inner0,
                                const float* __restrict__ inner1,
                                const float* __restrict__ S2,
                                const int*   __restrict__ ray_start,
                                float*       __restrict__ out,
                                int n, int nrays)
{
    const int r = (blockIdx.x * blockDim.x + threadIdx.x) >> 5;
    if (r >= nrays) return;
    const int lane = threadIdx.x & 31;

    const int s = ray_start[r];
    const int e = (r + 1 < nrays) ? ray_start[r + 1] : n;

    const float offset = __fsub_rn(S0_at(s, inner0, inner1, S2), loga[s]);

    float wsum = 0.0f, rs = 0.0f, gs = 0.0f, bs = 0.0f, lsum = 0.0f;

    for (int base = s; base < e; base += 32) {
        const int idx = base + lane;
        if (idx < e) {
            const float la  = loga[idx];
            const float S   = S0_at(idx, inner0, inner1, S2);
            const float ecs = __fsub_rn(S, la);                 // exclusive
            const float t   = expf(__fsub_rn(ecs, offset));     // transmittance
            const float w   = __fmul_rn(alpha[idx], t);
            wsum += w;
            rs   += w * rgb[3 * idx + 0];
            gs   += w * rgb[3 * idx + 1];
            bs   += w * rgb[3 * idx + 2];
            lsum += la;
        }
    }

    #pragma unroll
    for (int d = 16; d > 0; d >>= 1) {
        rs   += __shfl_down_sync(0xffffffffu, rs,   d);
        gs   += __shfl_down_sync(0xffffffffu, gs,   d);
        bs   += __shfl_down_sync(0xffffffffu, bs,   d);
        wsum += __shfl_down_sync(0xffffffffu, wsum, d);
        lsum += __shfl_down_sync(0xffffffffu, lsum, d);
    }

    if (lane == 0) {
        float* o = out + 5 * (size_t)r;
        o[0] = rs;
        o[1] = gs;
        o[2] = bs;
        o[3] = wsum;
        o[4] = expf(lsum);     // bg transmittance
    }
}

extern "C" void kernel_launch(void* const* d_in, const int* in_sizes, int n_in,
                              void* d_out, int out_size)
{
    const float* sigma     = (const float*)d_in[0];
    const float* dt        = (const float*)d_in[1];
    const float* rgb       = (const float*)d_in[2];
    const int*   ray_start = (const int*)d_in[4];
    float*       out       = (float*)d_out;

    const int n     = in_sizes[0];      // 8388608 = 16^5 * 8
    const int nrays = in_sizes[4];
    const int thr = 256;

    float *loga, *alpha, *inner0, *inner1, *r1, *r2, *S2, *t3, *t4, *t5, *s5;
    cudaGetSymbolAddress((void**)&loga,   g_loga);
    cudaGetSymbolAddress((void**)&alpha,  g_alpha);
    cudaGetSymbolAddress((void**)&inner0, g_inner0);
    cudaGetSymbolAddress((void**)&inner1, g_inner1);
    cudaGetSymbolAddress((void**)&r1,     g_r1);
    cudaGetSymbolAddress((void**)&r2,     g_r2);
    cudaGetSymbolAddress((void**)&S2,     g_S2);
    cudaGetSymbolAddress((void**)&t3,     g_t3);
    cudaGetSymbolAddress((void**)&t4,     g_t4);
    cudaGetSymbolAddress((void**)&t5,     g_t5);
    cudaGetSymbolAddress((void**)&s5,     g_s5);

    const int rows0 = n / BASE;         // 524288
    const int rows1 = rows0 / BASE;     // 32768

    // K1: fused prep + level-0 scan
    prep_scan0_kernel<<<(rows0 + thr - 1) / thr, thr>>>(
        (const float4*)sigma, (const float4*)dt,
        (float4*)loga, (float4*)alpha, (float4*)inner0, r1, rows0);

    // K2: level-1 scan over r1
    scan1_kernel<<<(rows1 + thr - 1) / thr, thr>>>(
        (const float4*)r1, (float4*)inner1, r2, rows1);

    // K3: all levels >= 2, single block (up + top + down)
    midscan_kernel<<<1, 1024>>>(r2, S2, t3, t4, t5, s5);

    // K4: finalize, warp per ray
    {
        int blk = (nrays * 32 + thr - 1) / thr;
        finalize_kernel<<<blk, thr>>>(rgb, loga, alpha, inner0, inner1, S2,
                                      ray_start, out, n, nrays);
    }
}